// round 3
// baseline (speedup 1.0000x reference)
#include <cuda_runtime.h>

#define N_VARS    100000
#define N_CLAUSES 400000
#define NNZ       1200000
#define D         128
#define EPSILON   1e-6f

// ---------------- scratch (static device globals) ---------------------------
// Edge record: 16B. For clause list: {next, var, val}. For var list: {next, clause, val}.
struct __align__(16) EdgeRec { int next; int idx; float val; int pad; };

__device__ float   g_S[(size_t)N_CLAUSES * D];   // clause sums, 204.8 MB
__device__ float   g_Sdeg[N_CLAUSES];            // clause degree column
__device__ int     g_head_c[N_CLAUSES];
__device__ int     g_head_v[N_VARS];
__device__ EdgeRec g_rec_c[NNZ];                 // 19.2 MB
__device__ EdgeRec g_rec_v[NNZ];                 // 19.2 MB

// ---------------- init: heads = -1 ------------------------------------------
__global__ void k_init() {
    int tid    = blockIdx.x * blockDim.x + threadIdx.x;
    int stride = gridDim.x * blockDim.x;
    for (int i = tid; i < N_CLAUSES; i += stride) g_head_c[i] = -1;
    for (int i = tid; i < N_VARS;    i += stride) g_head_v[i] = -1;
}

// ---------------- build both linked lists ------------------------------------
__global__ void k_build(const int* __restrict__ rows,
                        const int* __restrict__ cols,
                        const float* __restrict__ vals) {
    int e = blockIdx.x * blockDim.x + threadIdx.x;
    if (e >= NNZ) return;
    int   r  = __ldg(rows + e);
    int   c  = __ldg(cols + e);
    float vl = __ldg(vals + e);
    int   v  = (c >= N_VARS) ? (c - N_VARS) : c;   // fold literal halves

    int prev_c = atomicExch(&g_head_c[r], e);
    *reinterpret_cast<int4*>(&g_rec_c[e]) =
        make_int4(prev_c, v, __float_as_int(vl), 0);

    int prev_v = atomicExch(&g_head_v[v], e);
    *reinterpret_cast<int4*>(&g_rec_v[e]) =
        make_int4(prev_v, r, __float_as_int(vl), 0);
}

// ---------------- pass A: clause sums (warp per clause, plain stores) --------
__global__ void k_passA(const float* __restrict__ vars) {
    int w = (blockIdx.x * blockDim.x + threadIdx.x) >> 5;
    if (w >= N_CLAUSES) return;
    int lane = threadIdx.x & 31;

    int e = g_head_c[w];
    if (e < 0) return;   // empty clause: never read back, skip the write

    float4 sum = make_float4(0.f, 0.f, 0.f, 0.f);
    float  deg = 0.f;
    while (e >= 0) {
        int4 r = *reinterpret_cast<const int4*>(&g_rec_c[e]);  // broadcast load
        int   v   = r.y;
        float val = __int_as_float(r.z);
        float4 s = *reinterpret_cast<const float4*>(vars + (size_t)v * D + lane * 4);
        sum.x += s.x * val; sum.y += s.y * val;
        sum.z += s.z * val; sum.w += s.w * val;
        deg   += val;
        e = r.x;
    }
    *reinterpret_cast<float4*>(g_S + (size_t)w * D + lane * 4) = sum;
    if (lane == 0) g_Sdeg[w] = deg;
}

// ---------------- pass B: back-gather + fused normalize (warp per variable) --
__global__ void k_passB(const float* __restrict__ vars, float* __restrict__ out) {
    int w = (blockIdx.x * blockDim.x + threadIdx.x) >> 5;
    if (w >= N_VARS) return;
    int lane = threadIdx.x & 31;
    size_t off = (size_t)w * D + lane * 4;

    float4 acc = make_float4(0.f, 0.f, 0.f, 0.f);
    float  deg = 0.f;
    int e = g_head_v[w];
    while (e >= 0) {
        int4 r = *reinterpret_cast<const int4*>(&g_rec_v[e]);  // broadcast load
        int   c   = r.y;
        float val = __int_as_float(r.z);
        float4 s = *reinterpret_cast<const float4*>(g_S + (size_t)c * D + lane * 4);
        acc.x += s.x * val; acc.y += s.y * val;
        acc.z += s.z * val; acc.w += s.w * val;
        deg   += __ldg(g_Sdeg + c) * val;
        e = r.x;
    }

    float inv = 1.0f / fmaxf(deg, 2.0f);
    float4 x = *reinterpret_cast<const float4*>(vars + off);
    float4 vv = make_float4(x.x - acc.x * inv, x.y - acc.y * inv,
                            x.z - acc.z * inv, x.w - acc.w * inv);
    float ss = vv.x * vv.x + vv.y * vv.y + vv.z * vv.z + vv.w * vv.w;
    #pragma unroll
    for (int o = 16; o; o >>= 1) ss += __shfl_xor_sync(0xffffffffu, ss, o);
    float scale = rsqrtf(ss * (1.0f / 128.0f) + EPSILON);
    *reinterpret_cast<float4*>(out + off) =
        make_float4(vv.x * scale, vv.y * scale, vv.z * scale, vv.w * scale);
}

// ---------------- launcher ---------------------------------------------------
extern "C" void kernel_launch(void* const* d_in, const int* in_sizes, int n_in,
                              void* d_out, int out_size) {
    const float* vars = (const float*)d_in[0];
    const float* vals = (const float*)d_in[1];
    const int*   rows = (const int*)d_in[2];
    const int*   cols = (const int*)d_in[3];
    float* out = (float*)d_out;

    k_init <<<512, 256>>>();
    k_build<<<(NNZ + 255) / 256, 256>>>(rows, cols, vals);
    k_passA<<<(N_CLAUSES * 32 + 255) / 256, 256>>>(vars);
    k_passB<<<(N_VARS * 32 + 255) / 256, 256>>>(vars, out);
}